// round 11
// baseline (speedup 1.0000x reference)
#include <cuda_runtime.h>
#include <cuda_bf16.h>
#include <cstdint>

#define KN     8192
#define KD     8
#define NTHR   256
#define IPT    4
#define ITILE  1024          // i-rows per dom strip (IPT * NTHR)
#define TJ     64            // j-rows per dom tile
#define NSEG   8
#define SEGSZ  1024
#define NTILES 576           // per matrix: sum_{ti=0..7} 16*(ti+1)
#define NBLK   592           // 4 blocks/SM x 148 SMs (<= GB300's 152*4 slots)

// Device-global scratch. Statics start zeroed; every consumer re-zeroes or
// fully overwrites what it reads -> graph replays are deterministic.
__device__ unsigned       g_keys[16][KN];        // [m*8+d] segment-sorted keys
__device__ int            g_kidx[16][KN];        // original row id per seg-sorted pos
__device__ unsigned short g_rank16[2][KN][KD];   // per-row per-dim rank
__device__ uint4          g_prow[2][KN];         // packed fp16 rank rows, d0-rank order
__device__ int            g_counts[2 * KN];      // per sorted-row "neg" counts
__device__ int            g_hd[KN];              // signed diff histogram (A minus B)
__device__ unsigned       g_bar[4];              // grid barrier counters
__device__ unsigned       g_ctr;                 // final arrival counter

__device__ __forceinline__ unsigned f2sortable(float f) {
    unsigned u = __float_as_uint(f);
    return (u & 0x80000000u) ? ~u : (u | 0x80000000u);
}

// packed fp16x2 add (sign-exact for rank differences)
__device__ __forceinline__ unsigned hadd2(unsigned a, unsigned b) {
    unsigned d;
    asm("add.rn.f16x2 %0, %1, %2;" : "=r"(d) : "r"(a), "r"(b));
    return d;
}

// software grid barrier: all NBLK blocks are co-resident by construction
__device__ __forceinline__ void grid_bar(int i) {
    __syncthreads();
    if (threadIdx.x == 0) {
        __threadfence();                        // release this block's writes
        atomicAdd(&g_bar[i], 1u);
        volatile unsigned* p = &g_bar[i];
        while (*p < NBLK) __nanosleep(64);
    }
    __syncthreads();
    __threadfence();                            // acquire other blocks' writes
}

// ---------------------------------------------------------------------------
__global__ __launch_bounds__(256, 4) void kdm_mega(const float* __restrict__ X,
                                                   const float* __restrict__ Xh,
                                                   float* __restrict__ out) {
    __shared__ __align__(16) char sm_raw[32768];
    const int bid = blockIdx.x;
    const int tid = threadIdx.x;
    const int lane = tid & 31, wid = tid >> 5;

    // =======================================================================
    // P1) bitonic-sort 1024-element segments (128 tasks; 256 thr x 4 elems)
    // =======================================================================
    if (bid < 128) {
        const int md = bid >> 3;
        const int d  = md & 7;
        const float* __restrict__ src = (md >> 3) ? Xh : X;
        unsigned long long* s = (unsigned long long*)sm_raw;   // 8 KB
        const int e0 = (bid & 7) * SEGSZ;

        unsigned long long v[4];
        #pragma unroll
        for (int q = 0; q < 4; q++) {
            const int idx = q * 256 + tid;
            v[q] = ((unsigned long long)f2sortable(src[(size_t)(e0 + idx) * KD + d]) << 32)
                   | (unsigned)(e0 + idx);
        }

        #pragma unroll
        for (int k = 2; k <= SEGSZ; k <<= 1) {
            int j = k >> 1;
            #pragma unroll
            for (int jj = 512; jj >= 256; jj >>= 1) {
                if (jj <= (k >> 1)) {
                    const int dq = jj >> 8;
                    #pragma unroll
                    for (int qa = 0; qa < 4; qa++) {
                        if ((qa & dq) == 0) {
                            const int qb = qa | dq;
                            const bool up = (((qa * 256 + tid) & k) == 0);
                            const unsigned long long a = v[qa], b = v[qb];
                            if ((a > b) == up) { v[qa] = b; v[qb] = a; }
                        }
                    }
                    j = jj >> 1;
                }
            }
            while (j >= 32) {
                #pragma unroll
                for (int q = 0; q < 4; q++) s[q * 256 + tid] = v[q];
                __syncthreads();
                unsigned long long p[4];
                #pragma unroll
                for (int q = 0; q < 4; q++) p[q] = s[q * 256 + (tid ^ j)];
                __syncthreads();
                #pragma unroll
                for (int q = 0; q < 4; q++) {
                    const bool up   = (((q * 256 + tid) & k) == 0);
                    const bool low  = (tid & j) == 0;
                    const bool keepmin = (low == up);
                    const bool omin = (p[q] < v[q]);
                    v[q] = (keepmin == omin) ? p[q] : v[q];
                }
                j >>= 1;
            }
            #pragma unroll
            for (int jj = 16; jj >= 1; jj >>= 1) {
                if (jj <= (k >> 1)) {
                    #pragma unroll
                    for (int q = 0; q < 4; q++) {
                        const unsigned long long o = __shfl_xor_sync(0xffffffffu, v[q], jj);
                        const bool up   = (((q * 256 + tid) & k) == 0);
                        const bool low  = (tid & jj) == 0;
                        const bool keepmin = (low == up);
                        const bool omin = (o < v[q]);
                        v[q] = (keepmin == omin) ? o : v[q];
                    }
                }
            }
        }

        #pragma unroll
        for (int q = 0; q < 4; q++) {
            const unsigned long long r = v[q];
            g_keys[md][e0 + q * 256 + tid] = (unsigned)(r >> 32);
            g_kidx[md][e0 + q * 256 + tid] = (int)(unsigned)r;
        }
    }
    grid_bar(0);

    // =======================================================================
    // P2) global rank via cross-segment binary search (512 tasks)
    // =======================================================================
    if (bid < 512) {
        const int md    = bid >> 5;
        const int chunk = bid & 31;
        unsigned* sk = (unsigned*)sm_raw;   // 32 KB
        for (int k = tid; k < KN; k += 256) sk[k] = g_keys[md][k];
        __syncthreads();

        const int e   = chunk * 256 + tid;
        const int s   = e >> 10;
        const int pos = e & (SEGSZ - 1);
        const unsigned key = sk[e];

        int rank = pos;
        #pragma unroll
        for (int t = 0; t < NSEG; t++) {
            if (t == s) continue;
            const unsigned* seg = sk + t * SEGSZ;
            int lo = 0, hi = SEGSZ;
            if (t < s) {  // count <= key
                while (lo < hi) { const int mid = (lo + hi) >> 1; if (seg[mid] <= key) lo = mid + 1; else hi = mid; }
            } else {      // count < key
                while (lo < hi) { const int mid = (lo + hi) >> 1; if (seg[mid] <  key) lo = mid + 1; else hi = mid; }
            }
            rank += lo;
        }
        g_rank16[md >> 3][g_kidx[md][e]][md & 7] = (unsigned short)rank;
    }
    grid_bar(1);

    // =======================================================================
    // P3) pack dims 1..7 ranks (+0x400 fp16 bias) at the row's d0-rank (64 tasks)
    // =======================================================================
    if (bid < 64) {
        const int m   = bid >> 5;
        const int row = (bid & 31) * 256 + tid;
        const uint4 q = *reinterpret_cast<const uint4*>(&g_rank16[m][row][0]);
        const unsigned OFF = 0x04000400u;
        const unsigned d0 = q.x & 0xffffu;
        uint4 o;
        o.x = ((q.x >> 16) | (q.y << 16)) + OFF;   // d1, d2
        o.y = ((q.y >> 16) | (q.z << 16)) + OFF;   // d3, d4
        o.z = ((q.z >> 16) | (q.w << 16)) + OFF;   // d5, d6
        o.w = ( q.w >> 16)                + OFF;   // d7, pad
        g_prow[m][d0] = o;
    }
    grid_bar(2);

    // =======================================================================
    // P4) triangular dominance (2*NTILES tasks, grid-strided)
    // =======================================================================
    {
        uint4* sj = (uint4*)sm_raw;   // 1 KB
        for (int t = bid; t < 2 * NTILES; t += NBLK) {
            const int m = t / NTILES;
            const int b = t % NTILES;
            int ti = (int)(sqrtf((float)b * 0.125f + 0.25f));
            while (ti > 0 && 8 * ti * (ti + 1) > b) --ti;
            while (8 * (ti + 1) * (ti + 2) <= b) ++ti;
            const int tj = b - 8 * ti * (ti + 1);
            const int i0 = ti << 10;
            const int j0 = tj << 6;

            __syncthreads();   // previous tile's readers done before refill
            if (tid < TJ) {
                uint4 v = g_prow[m][j0 + tid];
                v.x ^= 0x80008000u; v.y ^= 0x80008000u;
                v.z ^= 0x80008000u; v.w ^= 0x80008000u;
                sj[tid] = v;
            }

            const int ib = i0 + tid;
            uint4 a[IPT];
            #pragma unroll
            for (int p = 0; p < IPT; p++) a[p] = g_prow[m][ib + p * NTHR];
            __syncthreads();

            unsigned neg[IPT] = {0, 0, 0, 0};

            if (j0 + TJ <= i0) {
                #pragma unroll 4
                for (int j = 0; j < TJ; j++) {
                    const uint4 bv = sj[j];
                    #pragma unroll
                    for (int p = 0; p < IPT; p++) {
                        const unsigned x0 = hadd2(a[p].x, bv.x);
                        const unsigned x1 = hadd2(a[p].y, bv.y);
                        const unsigned x2 = hadd2(a[p].z, bv.z);
                        const unsigned x3 = hadd2(a[p].w, bv.w);
                        const unsigned o  = x0 | x1 | x2;
                        const unsigned sb = (o | x3) & 0x80008000u;
                        if (sb) neg[p]++;
                    }
                }
            } else {
                int lim[IPT];
                #pragma unroll
                for (int p = 0; p < IPT; p++) lim[p] = ib + p * NTHR - j0;
                #pragma unroll 4
                for (int j = 0; j < TJ; j++) {
                    const uint4 bv = sj[j];
                    #pragma unroll
                    for (int p = 0; p < IPT; p++) {
                        const unsigned x0 = hadd2(a[p].x, bv.x);
                        const unsigned x1 = hadd2(a[p].y, bv.y);
                        const unsigned x2 = hadd2(a[p].z, bv.z);
                        const unsigned x3 = hadd2(a[p].w, bv.w);
                        const unsigned o  = x0 | x1 | x2;
                        const unsigned sb = (o | x3) & 0x80008000u;
                        neg[p] += min(sb, 1u) | (unsigned)(j >= lim[p]);
                    }
                }
            }

            #pragma unroll
            for (int p = 0; p < IPT; p++)
                atomicAdd(&g_counts[m * KN + ib + p * NTHR], (int)neg[p]);
        }
    }
    grid_bar(3);

    // =======================================================================
    // P5) histogram (64 tasks) + last-block W1 finalize
    // =======================================================================
    if (bid < 64) {
        const int slot = bid * 256 + tid;
        const int neg  = g_counts[slot];
        g_counts[slot] = 0;
        const int i = slot & (KN - 1);
        const int v = (((i >> 10) + 1) << 10) - neg;   // dominated count
        const int delta = (slot >= KN) ? -1 : 1;
        const unsigned mask = __match_any_sync(0xffffffffu, v);
        if ((int)(__ffs(mask) - 1) == lane)
            atomicAdd(&g_hd[v], delta * __popc(mask));
    }

    __syncthreads();
    __shared__ bool s_last;
    if (tid == 0) {
        __threadfence();
        s_last = (atomicAdd(&g_ctr, 1u) == NBLK - 1);
    }
    __syncthreads();
    if (!s_last) return;
    __threadfence();   // acquire all blocks' g_hd updates

    // ---- finalize: sum_t |cum diff(t)| / (N*(N-1)), 256 threads ----
    int* wsum = (int*)sm_raw;          // [8]
    int* asum = (int*)sm_raw + 16;     // [8]

    const int base = tid * 32;
    int d[32], tot = 0;
    #pragma unroll
    for (int k = 0; k < 32; k++) {
        d[k] = g_hd[base + k];
        g_hd[base + k] = 0;
        tot += d[k];
    }

    int v = tot;
    #pragma unroll
    for (int off = 1; off < 32; off <<= 1) {
        const int n = __shfl_up_sync(0xffffffffu, v, off);
        if (lane >= off) v += n;
    }
    if (lane == 31) wsum[wid] = v;
    __syncthreads();
    if (tid == 0) {
        int run = 0;
        #pragma unroll
        for (int w = 0; w < 8; w++) { const int x = wsum[w]; wsum[w] = run; run += x; }
    }
    __syncthreads();

    const int excl = v - tot + wsum[wid];
    int run = excl, acc = 0;
    #pragma unroll
    for (int k = 0; k < 32; k++) {
        run += d[k];
        acc += (run >= 0) ? run : -run;
    }

    #pragma unroll
    for (int off = 16; off; off >>= 1) acc += __shfl_down_sync(0xffffffffu, acc, off);
    if (lane == 0) asum[wid] = acc;
    __syncthreads();
    if (tid == 0) {
        int r = 0;
        #pragma unroll
        for (int w = 0; w < 8; w++) r += asum[w];
        out[0] = (float)r / ((float)KN * (float)(KN - 1));
        // reset for the next graph replay
        g_bar[0] = 0; g_bar[1] = 0; g_bar[2] = 0; g_bar[3] = 0;
        g_ctr = 0;
    }
}

// ---------------------------------------------------------------------------
extern "C" void kernel_launch(void* const* d_in, const int* in_sizes, int n_in,
                              void* d_out, int out_size) {
    const float* X  = (const float*)d_in[0];
    const float* Xh = (const float*)d_in[1];
    float* out = (float*)d_out;

    kdm_mega<<<NBLK, NTHR>>>(X, Xh, out);
}

// round 12
// speedup vs baseline: 1.1769x; 1.1769x over previous
#include <cuda_runtime.h>
#include <cuda_bf16.h>
#include <cstdint>

#define KN     8192
#define KD     8
#define NTHR   256
#define IPT    4
#define ITILE  1024          // i-rows per dom strip (IPT * NTHR)
#define TJ     64            // j-rows per dom tile
#define NSEG   8
#define SEGSZ  1024
#define NTILES 576           // per matrix: sum_{ti=0..7} 16*(ti+1)
#define ABLK   512           // prep kernel block count (co-resident: 3.5/SM)

// Device-global scratch. Statics start zeroed; every consumer re-zeroes or
// fully overwrites what it reads -> graph replays are deterministic.
__device__ unsigned       g_keys[16][KN];        // [m*8+d] segment-sorted keys
__device__ int            g_kidx[16][KN];        // original row id per seg-sorted pos
__device__ unsigned short g_rank16[2][KN][KD];   // per-row per-dim rank
__device__ uint4          g_prow[2][KN];         // packed fp16 rank rows, d0-rank order
__device__ int            g_counts[2 * KN];      // per sorted-row "neg" counts
__device__ int            g_hd[KN];              // signed diff histogram (A minus B)
__device__ unsigned       g_abar[2];             // prep-kernel grid barriers
__device__ unsigned       g_ctr;                 // finh arrival counter

__device__ __forceinline__ unsigned f2sortable(float f) {
    unsigned u = __float_as_uint(f);
    return (u & 0x80000000u) ? ~u : (u | 0x80000000u);
}

// packed fp16x2 add (sign-exact for rank differences)
__device__ __forceinline__ unsigned hadd2(unsigned a, unsigned b) {
    unsigned d;
    asm("add.rn.f16x2 %0, %1, %2;" : "=r"(d) : "r"(a), "r"(b));
    return d;
}

// software grid barrier for the prep kernel (ABLK co-resident blocks)
__device__ __forceinline__ void prep_bar(int i) {
    __syncthreads();
    if (threadIdx.x == 0) {
        __threadfence();                        // release this block's writes
        atomicAdd(&g_abar[i], 1u);
        volatile unsigned* p = &g_abar[i];
        while (*p < ABLK) __nanosleep(64);
    }
    __syncthreads();
    __threadfence();                            // acquire other blocks' writes
}

// ---------------------------------------------------------------------------
// A) fused prep: P1 segment bitonic sort -> P2 global rank -> P3 pack.
//    512 blocks x 256 threads; 2 grid barriers.
// ---------------------------------------------------------------------------
__global__ __launch_bounds__(256) void kdm_prep(const float* __restrict__ X,
                                                const float* __restrict__ Xh) {
    __shared__ __align__(16) char sm_raw[32768];
    const int bid = blockIdx.x;
    const int tid = threadIdx.x;

    // ===== P1: bitonic-sort 1024-element segments (blocks 0..127) =====
    if (bid < 128) {
        const int md = bid >> 3;
        const int d  = md & 7;
        const float* __restrict__ src = (md >> 3) ? Xh : X;
        unsigned long long* s = (unsigned long long*)sm_raw;   // 8 KB
        const int e0 = (bid & 7) * SEGSZ;

        unsigned long long v[4];
        #pragma unroll
        for (int q = 0; q < 4; q++) {
            const int idx = q * 256 + tid;
            v[q] = ((unsigned long long)f2sortable(src[(size_t)(e0 + idx) * KD + d]) << 32)
                   | (unsigned)(e0 + idx);
        }

        #pragma unroll
        for (int k = 2; k <= SEGSZ; k <<= 1) {
            int j = k >> 1;
            #pragma unroll
            for (int jj = 512; jj >= 256; jj >>= 1) {
                if (jj <= (k >> 1)) {
                    const int dq = jj >> 8;
                    #pragma unroll
                    for (int qa = 0; qa < 4; qa++) {
                        if ((qa & dq) == 0) {
                            const int qb = qa | dq;
                            const bool up = (((qa * 256 + tid) & k) == 0);
                            const unsigned long long a = v[qa], b = v[qb];
                            if ((a > b) == up) { v[qa] = b; v[qb] = a; }
                        }
                    }
                    j = jj >> 1;
                }
            }
            while (j >= 32) {
                #pragma unroll
                for (int q = 0; q < 4; q++) s[q * 256 + tid] = v[q];
                __syncthreads();
                unsigned long long p[4];
                #pragma unroll
                for (int q = 0; q < 4; q++) p[q] = s[q * 256 + (tid ^ j)];
                __syncthreads();
                #pragma unroll
                for (int q = 0; q < 4; q++) {
                    const bool up   = (((q * 256 + tid) & k) == 0);
                    const bool low  = (tid & j) == 0;
                    const bool keepmin = (low == up);
                    const bool omin = (p[q] < v[q]);
                    v[q] = (keepmin == omin) ? p[q] : v[q];
                }
                j >>= 1;
            }
            #pragma unroll
            for (int jj = 16; jj >= 1; jj >>= 1) {
                if (jj <= (k >> 1)) {
                    #pragma unroll
                    for (int q = 0; q < 4; q++) {
                        const unsigned long long o = __shfl_xor_sync(0xffffffffu, v[q], jj);
                        const bool up   = (((q * 256 + tid) & k) == 0);
                        const bool low  = (tid & jj) == 0;
                        const bool keepmin = (low == up);
                        const bool omin = (o < v[q]);
                        v[q] = (keepmin == omin) ? o : v[q];
                    }
                }
            }
        }

        #pragma unroll
        for (int q = 0; q < 4; q++) {
            const unsigned long long r = v[q];
            g_keys[md][e0 + q * 256 + tid] = (unsigned)(r >> 32);
            g_kidx[md][e0 + q * 256 + tid] = (int)(unsigned)r;
        }
    }
    prep_bar(0);

    // ===== P2: global rank via cross-segment binary search (all 512) =====
    {
        const int md    = bid >> 5;
        const int chunk = bid & 31;
        unsigned* sk = (unsigned*)sm_raw;   // 32 KB
        for (int k = tid; k < KN; k += 256) sk[k] = g_keys[md][k];
        __syncthreads();

        const int e   = chunk * 256 + tid;
        const int s   = e >> 10;
        const int pos = e & (SEGSZ - 1);
        const unsigned key = sk[e];

        int rank = pos;
        #pragma unroll
        for (int t = 0; t < NSEG; t++) {
            if (t == s) continue;
            const unsigned* seg = sk + t * SEGSZ;
            int lo = 0, hi = SEGSZ;
            if (t < s) {  // count <= key
                while (lo < hi) { const int mid = (lo + hi) >> 1; if (seg[mid] <= key) lo = mid + 1; else hi = mid; }
            } else {      // count < key
                while (lo < hi) { const int mid = (lo + hi) >> 1; if (seg[mid] <  key) lo = mid + 1; else hi = mid; }
            }
            rank += lo;
        }
        g_rank16[md >> 3][g_kidx[md][e]][md & 7] = (unsigned short)rank;
    }
    prep_bar(1);

    // ===== P3: pack fp16-biased ranks at the row's d0-rank (blocks 0..63) =====
    if (bid < 64) {
        const int m   = bid >> 5;
        const int row = (bid & 31) * 256 + tid;
        const uint4 q = *reinterpret_cast<const uint4*>(&g_rank16[m][row][0]);
        const unsigned OFF = 0x04000400u;
        const unsigned d0 = q.x & 0xffffu;
        uint4 o;
        o.x = ((q.x >> 16) | (q.y << 16)) + OFF;   // d1, d2
        o.y = ((q.y >> 16) | (q.z << 16)) + OFF;   // d3, d4
        o.z = ((q.z >> 16) | (q.w << 16)) + OFF;   // d5, d6
        o.w = ( q.w >> 16)                + OFF;   // d7, pad
        g_prow[m][d0] = o;
    }
}

// ---------------------------------------------------------------------------
// D) triangular dominance on rank-sorted packed rows (unchanged from best).
//    Thread owns 4 i-rows; strip ti has 16*(ti+1) j-tiles of 64.
// ---------------------------------------------------------------------------
__global__ __launch_bounds__(NTHR, 6) void kdm_dom() {
    const int m = blockIdx.y;
    const int b = blockIdx.x;
    int ti = (int)(sqrtf((float)b * 0.125f + 0.25f));
    while (ti > 0 && 8 * ti * (ti + 1) > b) --ti;
    while (8 * (ti + 1) * (ti + 2) <= b) ++ti;
    const int tj = b - 8 * ti * (ti + 1);
    const int i0 = ti << 10;
    const int j0 = tj << 6;

    __shared__ uint4 sj[TJ];    // 1 KB, fp16-negated j-rows

    if (threadIdx.x < TJ) {
        uint4 v = g_prow[m][j0 + threadIdx.x];
        v.x ^= 0x80008000u; v.y ^= 0x80008000u;
        v.z ^= 0x80008000u; v.w ^= 0x80008000u;
        sj[threadIdx.x] = v;
    }

    const int ib = i0 + threadIdx.x;
    uint4 a[IPT];
    #pragma unroll
    for (int p = 0; p < IPT; p++) a[p] = g_prow[m][ib + p * NTHR];
    __syncthreads();

    unsigned neg[IPT] = {0, 0, 0, 0};

    if (j0 + TJ <= i0) {
        #pragma unroll 4
        for (int j = 0; j < TJ; j++) {
            const uint4 bv = sj[j];
            #pragma unroll
            for (int p = 0; p < IPT; p++) {
                const unsigned x0 = hadd2(a[p].x, bv.x);
                const unsigned x1 = hadd2(a[p].y, bv.y);
                const unsigned x2 = hadd2(a[p].z, bv.z);
                const unsigned x3 = hadd2(a[p].w, bv.w);
                const unsigned o  = x0 | x1 | x2;
                const unsigned sb = (o | x3) & 0x80008000u;
                if (sb) neg[p]++;
            }
        }
    } else {
        int lim[IPT];
        #pragma unroll
        for (int p = 0; p < IPT; p++) lim[p] = ib + p * NTHR - j0;
        #pragma unroll 4
        for (int j = 0; j < TJ; j++) {
            const uint4 bv = sj[j];
            #pragma unroll
            for (int p = 0; p < IPT; p++) {
                const unsigned x0 = hadd2(a[p].x, bv.x);
                const unsigned x1 = hadd2(a[p].y, bv.y);
                const unsigned x2 = hadd2(a[p].z, bv.z);
                const unsigned x3 = hadd2(a[p].w, bv.w);
                const unsigned o  = x0 | x1 | x2;
                const unsigned sb = (o | x3) & 0x80008000u;
                neg[p] += min(sb, 1u) | (unsigned)(j >= lim[p]);
            }
        }
    }

    #pragma unroll
    for (int p = 0; p < IPT; p++)
        atomicAdd(&g_counts[m * KN + ib + p * NTHR], (int)neg[p]);
}

// ---------------------------------------------------------------------------
// FH) fused histogram + finalize (unchanged). 16 blocks of 1024; the last
//     block to arrive runs the W1 scan. Re-zeroes consumed scratch and the
//     prep barrier counters for the next graph replay.
// ---------------------------------------------------------------------------
__global__ __launch_bounds__(1024) void kdm_finh(float* __restrict__ out) {
    const int tid = threadIdx.x, lane = tid & 31, wid = tid >> 5;

    {   // histogram phase
        const int slot = blockIdx.x * 1024 + tid;
        const int neg  = g_counts[slot];
        g_counts[slot] = 0;
        const int i = slot & (KN - 1);
        const int v = (((i >> 10) + 1) << 10) - neg;   // dominated count
        const int delta = (slot >= KN) ? -1 : 1;
        const unsigned mask = __match_any_sync(0xffffffffu, v);
        if ((int)(__ffs(mask) - 1) == lane)
            atomicAdd(&g_hd[v], delta * __popc(mask));
    }

    __threadfence();
    __syncthreads();
    __shared__ bool s_last;
    if (tid == 0) s_last = (atomicAdd(&g_ctr, 1u) == gridDim.x - 1);
    __syncthreads();
    if (!s_last) return;
    __threadfence();   // acquire all blocks' g_hd updates

    __shared__ int wsum[32];
    const int base = tid * 8;
    int d[8], tot = 0;
    #pragma unroll
    for (int k = 0; k < 8; k++) {
        d[k] = g_hd[base + k];
        g_hd[base + k] = 0;
        tot += d[k];
    }

    int v = tot;
    #pragma unroll
    for (int off = 1; off < 32; off <<= 1) {
        const int n = __shfl_up_sync(0xffffffffu, v, off);
        if (lane >= off) v += n;
    }
    if (lane == 31) wsum[wid] = v;
    __syncthreads();
    if (wid == 0) {
        int w = wsum[lane];
        #pragma unroll
        for (int off = 1; off < 32; off <<= 1) {
            const int n = __shfl_up_sync(0xffffffffu, w, off);
            if (lane >= off) w += n;
        }
        wsum[lane] = w;
    }
    __syncthreads();

    const int excl = v - tot + (wid ? wsum[wid - 1] : 0);
    int run = excl, acc = 0;
    #pragma unroll
    for (int k = 0; k < 8; k++) {
        run += d[k];
        acc += (run >= 0) ? run : -run;
    }

    #pragma unroll
    for (int off = 16; off; off >>= 1) acc += __shfl_down_sync(0xffffffffu, acc, off);
    __syncthreads();
    if (lane == 0) wsum[wid] = acc;
    __syncthreads();
    if (wid == 0) {
        int r = wsum[lane];
        #pragma unroll
        for (int off = 16; off; off >>= 1) r += __shfl_down_sync(0xffffffffu, r, off);
        if (lane == 0) {
            out[0] = (float)r / ((float)KN * (float)(KN - 1));
            g_ctr = 0;                    // reset for next graph replay
            g_abar[0] = 0; g_abar[1] = 0; // reset prep barriers
        }
    }
}

// ---------------------------------------------------------------------------
extern "C" void kernel_launch(void* const* d_in, const int* in_sizes, int n_in,
                              void* d_out, int out_size) {
    const float* X  = (const float*)d_in[0];
    const float* Xh = (const float*)d_in[1];
    float* out = (float*)d_out;

    kdm_prep<<<ABLK, NTHR>>>(X, Xh);
    kdm_dom <<<dim3(NTILES, 2), NTHR>>>();
    kdm_finh<<<2 * KN / 1024, 1024>>>(out);
}

// round 13
// speedup vs baseline: 1.2697x; 1.0788x over previous
#include <cuda_runtime.h>
#include <cuda_bf16.h>
#include <cstdint>

#define KN     8192
#define KD     8
#define NTHR   256
#define IPT    4
#define ITILE  1024          // i-rows per dom strip (IPT * NTHR)
#define TJ     64            // j-rows per dom tile
#define NSEG   8
#define SEGSZ  1024
#define NTILES 576           // per matrix: sum_{ti=0..7} 16*(ti+1)

// Device-global scratch. Statics start zeroed; every consumer re-zeroes or
// fully overwrites what it reads -> graph replays are deterministic.
__device__ unsigned       g_keys[16][KN];        // [m*8+d] segment-sorted keys
__device__ int            g_kidx[16][KN];        // original row id per seg-sorted pos
__device__ unsigned short g_rank16[2][KN][KD];   // per-row per-dim rank
__device__ uint4          g_prow[2][KN];         // packed fp16 rank rows, d0-rank order
__device__ int            g_counts[2 * KN];      // per sorted-row "neg" counts
__device__ int            g_hd[KN];              // signed diff histogram (A minus B)
__device__ unsigned       g_ctr;                 // finh arrival counter

__device__ __forceinline__ unsigned f2sortable(float f) {
    unsigned u = __float_as_uint(f);
    return (u & 0x80000000u) ? ~u : (u | 0x80000000u);
}

// packed fp16x2 add (sign-exact for rank differences)
__device__ __forceinline__ unsigned hadd2(unsigned a, unsigned b) {
    unsigned d;
    asm("add.rn.f16x2 %0, %1, %2;" : "=r"(d) : "r"(a), "r"(b));
    return d;
}

// ---------------------------------------------------------------------------
// S1) bitonic-sort 1024-element segments, 256 threads x 4 elements.
//     Distances >=256: in-register; 32..128: smem; <=16: shfl.
// ---------------------------------------------------------------------------
__global__ __launch_bounds__(256) void kdm_sort_seg(const float* __restrict__ X,
                                                    const float* __restrict__ Xh) {
    const int md = blockIdx.y;
    const int d  = md & 7;
    const float* __restrict__ src = (md >> 3) ? Xh : X;
    __shared__ unsigned long long s[SEGSZ];   // 8 KB
    const int t  = threadIdx.x;
    const int e0 = blockIdx.x * SEGSZ;

    unsigned long long v[4];
    #pragma unroll
    for (int q = 0; q < 4; q++) {
        const int idx = q * 256 + t;
        v[q] = ((unsigned long long)f2sortable(src[(size_t)(e0 + idx) * KD + d]) << 32)
               | (unsigned)(e0 + idx);
    }

    #pragma unroll
    for (int k = 2; k <= SEGSZ; k <<= 1) {
        int j = k >> 1;
        #pragma unroll
        for (int jj = 512; jj >= 256; jj >>= 1) {
            if (jj <= (k >> 1)) {
                const int dq = jj >> 8;
                #pragma unroll
                for (int qa = 0; qa < 4; qa++) {
                    if ((qa & dq) == 0) {
                        const int qb = qa | dq;
                        const bool up = (((qa * 256 + t) & k) == 0);
                        const unsigned long long a = v[qa], b = v[qb];
                        if ((a > b) == up) { v[qa] = b; v[qb] = a; }
                    }
                }
                j = jj >> 1;
            }
        }
        while (j >= 32) {
            #pragma unroll
            for (int q = 0; q < 4; q++) s[q * 256 + t] = v[q];
            __syncthreads();
            unsigned long long p[4];
            #pragma unroll
            for (int q = 0; q < 4; q++) p[q] = s[q * 256 + (t ^ j)];
            __syncthreads();
            #pragma unroll
            for (int q = 0; q < 4; q++) {
                const bool up   = (((q * 256 + t) & k) == 0);
                const bool low  = (t & j) == 0;
                const bool keepmin = (low == up);
                const bool omin = (p[q] < v[q]);
                v[q] = (keepmin == omin) ? p[q] : v[q];
            }
            j >>= 1;
        }
        #pragma unroll
        for (int jj = 16; jj >= 1; jj >>= 1) {
            if (jj <= (k >> 1)) {
                #pragma unroll
                for (int q = 0; q < 4; q++) {
                    const unsigned long long o = __shfl_xor_sync(0xffffffffu, v[q], jj);
                    const bool up   = (((q * 256 + t) & k) == 0);
                    const bool low  = (t & jj) == 0;
                    const bool keepmin = (low == up);
                    const bool omin = (o < v[q]);
                    v[q] = (keepmin == omin) ? o : v[q];
                }
            }
        }
    }

    #pragma unroll
    for (int q = 0; q < 4; q++) {
        const unsigned long long r = v[q];
        g_keys[md][e0 + q * 256 + t] = (unsigned)(r >> 32);
        g_kidx[md][e0 + q * 256 + t] = (int)(unsigned)r;
    }
}

// ---------------------------------------------------------------------------
// S2) global rank via cross-segment binary search; PDL-synced on sort.
// ---------------------------------------------------------------------------
__global__ __launch_bounds__(256) void kdm_rank() {
    const int md = blockIdx.y;
    const int e  = blockIdx.x * 256 + threadIdx.x;
    const int s  = e >> 10;
    const int pos = e & (SEGSZ - 1);

    cudaGridDependencySynchronize();   // wait for kdm_sort_seg's g_keys/g_kidx

    __shared__ unsigned sk[KN];   // 32 KB
    for (int k = threadIdx.x; k < KN; k += 256) sk[k] = g_keys[md][k];
    __syncthreads();

    const unsigned key = sk[e];
    int rank = pos;
    #pragma unroll
    for (int t = 0; t < NSEG; t++) {
        if (t == s) continue;
        const unsigned* seg = sk + t * SEGSZ;
        int lo = 0, hi = SEGSZ;
        if (t < s) {  // count <= key
            while (lo < hi) { const int mid = (lo + hi) >> 1; if (seg[mid] <= key) lo = mid + 1; else hi = mid; }
        } else {      // count < key
            while (lo < hi) { const int mid = (lo + hi) >> 1; if (seg[mid] <  key) lo = mid + 1; else hi = mid; }
        }
        rank += lo;
    }
    g_rank16[md >> 3][g_kidx[md][e]][md & 7] = (unsigned short)rank;
}

// ---------------------------------------------------------------------------
// S3) pack dims 1..7 ranks (+0x400 fp16 bias) at the row's d0-rank position.
// ---------------------------------------------------------------------------
__global__ __launch_bounds__(256) void kdm_pack() {
    const int m   = blockIdx.y;
    const int row = blockIdx.x * 256 + threadIdx.x;

    cudaGridDependencySynchronize();   // wait for kdm_rank's g_rank16

    const uint4 q = *reinterpret_cast<const uint4*>(&g_rank16[m][row][0]);
    const unsigned OFF = 0x04000400u;
    const unsigned d0 = q.x & 0xffffu;
    uint4 o;
    o.x = ((q.x >> 16) | (q.y << 16)) + OFF;   // d1, d2
    o.y = ((q.y >> 16) | (q.z << 16)) + OFF;   // d3, d4
    o.z = ((q.z >> 16) | (q.w << 16)) + OFF;   // d5, d6
    o.w = ( q.w >> 16)                + OFF;   // d7, pad
    g_prow[m][d0] = o;
}

// ---------------------------------------------------------------------------
// D) triangular dominance on rank-sorted packed rows. Thread owns 4 i-rows;
//    strip ti has 16*(ti+1) j-tiles of 64; start(ti) = 8*ti*(ti+1).
// ---------------------------------------------------------------------------
__global__ __launch_bounds__(NTHR, 6) void kdm_dom() {
    const int m = blockIdx.y;
    const int b = blockIdx.x;
    int ti = (int)(sqrtf((float)b * 0.125f + 0.25f));
    while (ti > 0 && 8 * ti * (ti + 1) > b) --ti;
    while (8 * (ti + 1) * (ti + 2) <= b) ++ti;
    const int tj = b - 8 * ti * (ti + 1);
    const int i0 = ti << 10;
    const int j0 = tj << 6;
    const int ib = i0 + threadIdx.x;

    cudaGridDependencySynchronize();   // wait for kdm_pack's g_prow

    __shared__ uint4 sj[TJ];    // 1 KB, fp16-negated j-rows
    if (threadIdx.x < TJ) {
        uint4 v = g_prow[m][j0 + threadIdx.x];
        v.x ^= 0x80008000u; v.y ^= 0x80008000u;
        v.z ^= 0x80008000u; v.w ^= 0x80008000u;
        sj[threadIdx.x] = v;
    }

    uint4 a[IPT];
    #pragma unroll
    for (int p = 0; p < IPT; p++) a[p] = g_prow[m][ib + p * NTHR];
    __syncthreads();

    unsigned neg[IPT] = {0, 0, 0, 0};

    if (j0 + TJ <= i0) {
        #pragma unroll 4
        for (int j = 0; j < TJ; j++) {
            const uint4 bv = sj[j];
            #pragma unroll
            for (int p = 0; p < IPT; p++) {
                const unsigned x0 = hadd2(a[p].x, bv.x);
                const unsigned x1 = hadd2(a[p].y, bv.y);
                const unsigned x2 = hadd2(a[p].z, bv.z);
                const unsigned x3 = hadd2(a[p].w, bv.w);
                const unsigned o  = x0 | x1 | x2;
                const unsigned sb = (o | x3) & 0x80008000u;
                if (sb) neg[p]++;
            }
        }
    } else {
        int lim[IPT];
        #pragma unroll
        for (int p = 0; p < IPT; p++) lim[p] = ib + p * NTHR - j0;
        #pragma unroll 4
        for (int j = 0; j < TJ; j++) {
            const uint4 bv = sj[j];
            #pragma unroll
            for (int p = 0; p < IPT; p++) {
                const unsigned x0 = hadd2(a[p].x, bv.x);
                const unsigned x1 = hadd2(a[p].y, bv.y);
                const unsigned x2 = hadd2(a[p].z, bv.z);
                const unsigned x3 = hadd2(a[p].w, bv.w);
                const unsigned o  = x0 | x1 | x2;
                const unsigned sb = (o | x3) & 0x80008000u;
                neg[p] += min(sb, 1u) | (unsigned)(j >= lim[p]);
            }
        }
    }

    #pragma unroll
    for (int p = 0; p < IPT; p++)
        atomicAdd(&g_counts[m * KN + ib + p * NTHR], (int)neg[p]);
}

// ---------------------------------------------------------------------------
// FH) fused histogram + finalize. 16 blocks of 1024; last block to arrive
//     runs the W1 scan. Re-zeroes consumed scratch for the next replay.
// ---------------------------------------------------------------------------
__global__ __launch_bounds__(1024) void kdm_finh(float* __restrict__ out) {
    const int tid = threadIdx.x, lane = tid & 31, wid = tid >> 5;

    cudaGridDependencySynchronize();   // wait for kdm_dom's g_counts

    {   // histogram phase
        const int slot = blockIdx.x * 1024 + tid;
        const int neg  = g_counts[slot];
        g_counts[slot] = 0;
        const int i = slot & (KN - 1);
        const int v = (((i >> 10) + 1) << 10) - neg;   // dominated count
        const int delta = (slot >= KN) ? -1 : 1;
        const unsigned mask = __match_any_sync(0xffffffffu, v);
        if ((int)(__ffs(mask) - 1) == lane)
            atomicAdd(&g_hd[v], delta * __popc(mask));
    }

    __threadfence();
    __syncthreads();
    __shared__ bool s_last;
    if (tid == 0) s_last = (atomicAdd(&g_ctr, 1u) == gridDim.x - 1);
    __syncthreads();
    if (!s_last) return;
    __threadfence();   // acquire all blocks' g_hd updates

    __shared__ int wsum[32];
    const int base = tid * 8;
    int d[8], tot = 0;
    #pragma unroll
    for (int k = 0; k < 8; k++) {
        d[k] = g_hd[base + k];
        g_hd[base + k] = 0;
        tot += d[k];
    }

    int v = tot;
    #pragma unroll
    for (int off = 1; off < 32; off <<= 1) {
        const int n = __shfl_up_sync(0xffffffffu, v, off);
        if (lane >= off) v += n;
    }
    if (lane == 31) wsum[wid] = v;
    __syncthreads();
    if (wid == 0) {
        int w = wsum[lane];
        #pragma unroll
        for (int off = 1; off < 32; off <<= 1) {
            const int n = __shfl_up_sync(0xffffffffu, w, off);
            if (lane >= off) w += n;
        }
        wsum[lane] = w;
    }
    __syncthreads();

    const int excl = v - tot + (wid ? wsum[wid - 1] : 0);
    int run = excl, acc = 0;
    #pragma unroll
    for (int k = 0; k < 8; k++) {
        run += d[k];
        acc += (run >= 0) ? run : -run;
    }

    #pragma unroll
    for (int off = 16; off; off >>= 1) acc += __shfl_down_sync(0xffffffffu, acc, off);
    __syncthreads();
    if (lane == 0) wsum[wid] = acc;
    __syncthreads();
    if (wid == 0) {
        int r = wsum[lane];
        #pragma unroll
        for (int off = 16; off; off >>= 1) r += __shfl_down_sync(0xffffffffu, r, off);
        if (lane == 0) {
            out[0] = (float)r / ((float)KN * (float)(KN - 1));
            g_ctr = 0;   // reset for next graph replay
        }
    }
}

// ---------------------------------------------------------------------------
// Host: launch chain with PDL (programmatic stream serialization) so each
// downstream kernel's blocks are scheduled while the predecessor drains.
// ---------------------------------------------------------------------------
template <typename F, typename... Args>
static void launch_pdl(F f, dim3 grid, dim3 block, Args... args) {
    cudaLaunchConfig_t cfg = {};
    cfg.gridDim  = grid;
    cfg.blockDim = block;
    cfg.dynamicSmemBytes = 0;
    cfg.stream = 0;
    cudaLaunchAttribute attr[1];
    attr[0].id = cudaLaunchAttributeProgrammaticStreamSerialization;
    attr[0].val.programmaticStreamSerializationAllowed = 1;
    cfg.attrs = attr;
    cfg.numAttrs = 1;
    cudaLaunchKernelEx(&cfg, f, args...);
}

extern "C" void kernel_launch(void* const* d_in, const int* in_sizes, int n_in,
                              void* d_out, int out_size) {
    const float* X  = (const float*)d_in[0];
    const float* Xh = (const float*)d_in[1];
    float* out = (float*)d_out;

    kdm_sort_seg<<<dim3(NSEG, 16), 256>>>(X, Xh);
    launch_pdl(kdm_rank, dim3(KN / 256, 16), dim3(256));
    launch_pdl(kdm_pack, dim3(KN / 256, 2),  dim3(256));
    launch_pdl(kdm_dom,  dim3(NTILES, 2),    dim3(NTHR));
    launch_pdl(kdm_finh, dim3(2 * KN / 1024), dim3(1024), out);
}